// round 4
// baseline (speedup 1.0000x reference)
#include <cuda_runtime.h>
#include <cstdint>

// Problem constants
#define B_  32
#define I_  512
#define F_  321
#define O_  720
#define R_  (B_ * I_)          // 16384 rows of the (b,i) x f matrix
#define EPSV 1e-5f

// GEMM tiling
#define BN      120            // o-tile (720 = 6*120, exact)
#define KI      32             // k chunk
#define NCHUNK  (I_ / KI)      // 16
#define XS_STRIDE 516          // 512 + 4 pad -> conflict-free per-lane LDS.128
#define XS_FLOATS (B_ * XS_STRIDE)        // 16512
#define WS_FLOATS (BN * KI)               // 3840 per buffer
#define SMEM_FLOATS (XS_FLOATS + 2 * WS_FLOATS)
#define SMEM_BYTES  (SMEM_FLOATS * 4)     // 96768 B -> 2 CTAs/SM

// 21 MB scratch: normalized x transposed to [f][b][i] (i contiguous)
__device__ float g_xt[(size_t)F_ * R_];

// ---------------------------------------------------------------------------
// Kernel 1: normalize + transpose  x[b,i,f] -> g_xt[f, b*512+i]
// Tiled 32x32 transpose; each load-phase thread owns one f so the BN affine
// params are computed once per thread.
// ---------------------------------------------------------------------------
__global__ void norm_transpose_kernel(const float* __restrict__ x,
                                      const float* __restrict__ gamma,
                                      const float* __restrict__ beta,
                                      const float* __restrict__ rmean,
                                      const float* __restrict__ rvar)
{
    __shared__ float s[32][33];
    const int f0 = blockIdx.x * 32;
    const int r0 = blockIdx.y * 32;
    const int tx = threadIdx.x;
    const int ty = threadIdx.y;

    const int f = f0 + tx;
    float inv = 0.f, shift = 0.f;
    if (f < F_) {
        inv   = gamma[f] * rsqrtf(rvar[f] + EPSV);
        shift = beta[f] - rmean[f] * inv;
    }
#pragma unroll
    for (int k = 0; k < 4; k++) {
        const int rl = ty + k * 8;
        const size_t r = (size_t)(r0 + rl);
        float v = (f < F_) ? x[r * F_ + f] : 0.f;
        s[rl][tx] = v * inv + shift;
    }
    __syncthreads();
#pragma unroll
    for (int k = 0; k < 4; k++) {
        const int fl = ty + k * 8;
        const int ff = f0 + fl;
        if (ff < F_)
            g_xt[(size_t)ff * R_ + (size_t)(r0 + tx)] = s[tx][fl];
    }
}

// ---------------------------------------------------------------------------
// Kernel 2: per-f GEMM  out[b,o,f] = sum_i xt[f,b,i] * W[f,o,i] + bias[f,o]
// grid = (6 o-tiles, 321 f). lane = b, warp owns 15 o's.
// Xn_f fully resident in smem (padded); W double-buffered via cp.async.
// ---------------------------------------------------------------------------
__device__ __forceinline__ void cp_async16(uint32_t dst, const void* src) {
    asm volatile("cp.async.cg.shared.global [%0], [%1], 16;\n"
                 :: "r"(dst), "l"(src));
}
__device__ __forceinline__ void cp_commit() {
    asm volatile("cp.async.commit_group;\n");
}
template <int N>
__device__ __forceinline__ void cp_wait() {
    asm volatile("cp.async.wait_group %0;\n" :: "n"(N));
}

__global__ void __launch_bounds__(256, 2)
gemm_kernel(const float* __restrict__ W,
            const float* __restrict__ bias,
            float* __restrict__ out)
{
    extern __shared__ float sm[];
    float* xs = sm;                         // [32][XS_STRIDE]
    float* ws = sm + XS_FLOATS;             // [2][BN][KI]

    const int f    = blockIdx.y;
    const int ot   = blockIdx.x * BN;
    const int tid  = threadIdx.x;
    const int lane = tid & 31;              // = b
    const int warp = tid >> 5;              // o-group (15 o's)

    const float* __restrict__ Wf = W + (size_t)f * (O_ * I_);
    const float* __restrict__ xt = g_xt + (size_t)f * R_;

    const uint32_t ws_smem = (uint32_t)__cvta_generic_to_shared(ws);

    // Prologue: start chunk 0 of W streaming in
    {
        const size_t gbase = (size_t)ot * I_;  // + o_l*512 + gi
#pragma unroll 4
        for (int v = tid; v < BN * (KI / 4); v += 256) {   // 960 float4s
            const int o_l = v >> 3;
            const int gi  = (v & 7) << 2;
            cp_async16(ws_smem + (uint32_t)(o_l * KI + gi) * 4,
                       Wf + gbase + (size_t)o_l * I_ + gi);
        }
        cp_commit();
    }

    // Stage the full Xn_f tile (32 x 512) into padded smem
    for (int j = tid; j < R_ / 4; j += 256) {             // 4096 float4s
        const int b  = j >> 7;                            // j / 128
        const int iv = (j & 127) << 2;
        float4 v = reinterpret_cast<const float4*>(xt)[j];
        *reinterpret_cast<float4*>(xs + b * XS_STRIDE + iv) = v;
    }

    float acc[15];
#pragma unroll
    for (int j = 0; j < 15; j++) acc[j] = 0.f;

    const float* xrow_base = xs + lane * XS_STRIDE;
    const int    wofs      = warp * 15 * KI;

    for (int c = 0; c < NCHUNK; c++) {
        // Kick off next chunk into the other buffer, then wait for current
        if (c + 1 < NCHUNK) {
            const uint32_t dstb = ws_smem + (uint32_t)(((c + 1) & 1) * WS_FLOATS) * 4;
            const size_t gbase = (size_t)ot * I_ + (size_t)(c + 1) * KI;
#pragma unroll 4
            for (int v = tid; v < BN * (KI / 4); v += 256) {
                const int o_l = v >> 3;
                const int gi  = (v & 7) << 2;
                cp_async16(dstb + (uint32_t)(o_l * KI + gi) * 4,
                           Wf + gbase + (size_t)o_l * I_ + gi);
            }
            cp_commit();
            cp_wait<1>();
        } else {
            cp_wait<0>();
        }
        __syncthreads();

        const float* xrow = xrow_base + c * KI;
        const float* wbuf = ws + (c & 1) * WS_FLOATS + wofs;
#pragma unroll
        for (int i4 = 0; i4 < KI / 4; i4++) {
            const float4 a = *reinterpret_cast<const float4*>(xrow + i4 * 4);
#pragma unroll
            for (int j = 0; j < 15; j++) {
                const float4 w4 =
                    *reinterpret_cast<const float4*>(wbuf + j * KI + i4 * 4);
                acc[j] = fmaf(a.x, w4.x, acc[j]);
                acc[j] = fmaf(a.y, w4.y, acc[j]);
                acc[j] = fmaf(a.z, w4.z, acc[j]);
                acc[j] = fmaf(a.w, w4.w, acc[j]);
            }
        }
        __syncthreads();
    }

    // Epilogue: out[b, o, f] += bias[f, o]
    const int b  = lane;
    const int o0 = ot + warp * 15;
    const size_t obase = (size_t)b * O_ * F_ + (size_t)f;
    const float* bf = bias + (size_t)f * O_ + o0;
#pragma unroll
    for (int j = 0; j < 15; j++) {
        out[obase + (size_t)(o0 + j) * F_] = acc[j] + bf[j];
    }
}

// ---------------------------------------------------------------------------
// Launch
// ---------------------------------------------------------------------------
extern "C" void kernel_launch(void* const* d_in, const int* in_sizes, int n_in,
                              void* d_out, int out_size)
{
    const float* x     = (const float*)d_in[0];
    const float* W     = (const float*)d_in[1];
    const float* bias  = (const float*)d_in[2];
    const float* gamma = (const float*)d_in[3];
    const float* beta  = (const float*)d_in[4];
    const float* rmean = (const float*)d_in[5];
    const float* rvar  = (const float*)d_in[6];
    float* out = (float*)d_out;

    (void)in_sizes; (void)n_in; (void)out_size;

    // Not a stream op; safe during graph capture (executes immediately).
    cudaFuncSetAttribute(gemm_kernel,
                         cudaFuncAttributeMaxDynamicSharedMemorySize,
                         SMEM_BYTES);

    dim3 g1((F_ + 31) / 32, R_ / 32);       // (11, 512)
    norm_transpose_kernel<<<g1, dim3(32, 8)>>>(x, gamma, beta, rmean, rvar);

    dim3 g2(O_ / BN, F_);                    // (6, 321)
    gemm_kernel<<<g2, 256, SMEM_BYTES>>>(W, bias, out);
}

// round 9
// speedup vs baseline: 1.0137x; 1.0137x over previous
#include <cuda_runtime.h>
#include <cuda_bf16.h>
#include <cstdint>

// Problem constants
#define B_   32
#define I_   512
#define F_   321
#define O_   720
#define OPAD 768
#define R_   (B_ * I_)
#define EPSV 1e-5f

// GEMM tiling
#define OT   128          // o rows per CTA
#define KC   64           // k per chunk
#define NC   (I_ / KC)    // 8 chunks
#define NST  3            // cp.async pipeline stages for W

// Padded smem strides (conflict-free fragment loads)
#define WST_STRIDE_F 68                      // fp32 staging row: 68 floats (272B)
#define WST_BYTES    (OT * WST_STRIDE_F * 4) // 34816 per stage
#define WBF_STRIDE_B 144                     // bf16 W row: 72 bf16 (144B)
#define WBF_BYTES    (OT * WBF_STRIDE_B)     // 18432
#define XS_STRIDE_B  1040                    // bf16 x row: 520 bf16 (1040B)
#define XS_BYTES     (B_ * XS_STRIDE_B)      // 33280

// smem layout (bytes)
#define SM_WST 0
#define SM_WHI (SM_WST + NST * WST_BYTES)    // 104448
#define SM_WLO (SM_WHI + WBF_BYTES)          // 122880
#define SM_XHI (SM_WLO + WBF_BYTES)          // 141312
#define SM_XLO (SM_XHI + XS_BYTES)           // 174592
#define SMEM_BYTES (SM_XLO + XS_BYTES)       // 207872

// device scratch
__device__ __align__(16) __nv_bfloat16 g_xhi[(size_t)F_ * R_];
__device__ __align__(16) __nv_bfloat16 g_xlo[(size_t)F_ * R_];
__device__ __align__(16) float         g_out[(size_t)F_ * OPAD * B_];

// ---- helpers ----
__device__ __forceinline__ uint32_t smem_u32(const void* p) {
    uint32_t a;
    asm("{ .reg .u64 t; cvta.to.shared.u64 t, %1; cvt.u32.u64 %0, t; }"
        : "=r"(a) : "l"(p));
    return a;
}
__device__ __forceinline__ void cp16(uint32_t dst, const void* src) {
    asm volatile("cp.async.cg.shared.global [%0], [%1], 16;\n" :: "r"(dst), "l"(src));
}
__device__ __forceinline__ void cp_commit() {
    asm volatile("cp.async.commit_group;\n");
}
template <int N>
__device__ __forceinline__ void cp_wait() {
    asm volatile("cp.async.wait_group %0;\n" :: "n"(N));
}
__device__ __forceinline__ uint32_t lds32(const char* p) {
    return *reinterpret_cast<const uint32_t*>(p);
}
__device__ __forceinline__ void mma16816(float* acc, const uint32_t a[4],
                                         uint32_t b0, uint32_t b1) {
    asm volatile(
        "mma.sync.aligned.m16n8k16.row.col.f32.bf16.bf16.f32 "
        "{%0,%1,%2,%3}, {%4,%5,%6,%7}, {%8,%9}, {%0,%1,%2,%3};\n"
        : "+f"(acc[0]), "+f"(acc[1]), "+f"(acc[2]), "+f"(acc[3])
        : "r"(a[0]), "r"(a[1]), "r"(a[2]), "r"(a[3]), "r"(b0), "r"(b1));
}
__device__ __forceinline__ uint32_t pack_bf2(__nv_bfloat16 a, __nv_bfloat16 b) {
    __nv_bfloat162 p = __halves2bfloat162(a, b);
    return *reinterpret_cast<uint32_t*>(&p);
}

// ---------------------------------------------------------------------------
// Kernel 1: normalize + transpose + bf16 hi/lo split
// x[b,i,f] -> g_xhi/g_xlo[f, b*512+i]
// ---------------------------------------------------------------------------
__global__ void norm_transpose_kernel(const float* __restrict__ x,
                                      const float* __restrict__ gamma,
                                      const float* __restrict__ beta,
                                      const float* __restrict__ rmean,
                                      const float* __restrict__ rvar)
{
    __shared__ float s[32][33];
    const int f0 = blockIdx.x * 32;
    const int r0 = blockIdx.y * 32;
    const int tx = threadIdx.x, ty = threadIdx.y;

    const int f = f0 + tx;
    float inv = 0.f, shift = 0.f;
    if (f < F_) {
        inv   = gamma[f] * rsqrtf(rvar[f] + EPSV);
        shift = beta[f] - rmean[f] * inv;
    }
#pragma unroll
    for (int k = 0; k < 4; k++) {
        const int rl = ty + k * 8;
        float v = (f < F_) ? x[(size_t)(r0 + rl) * F_ + f] : 0.f;
        s[rl][tx] = v * inv + shift;
    }
    __syncthreads();
#pragma unroll
    for (int k = 0; k < 4; k++) {
        const int fl = ty + k * 8;
        const int ff = f0 + fl;
        if (ff < F_) {
            const float v = s[tx][fl];
            const __nv_bfloat16 hi = __float2bfloat16(v);
            const __nv_bfloat16 lo = __float2bfloat16(v - __bfloat162float(hi));
            const size_t idx = (size_t)ff * R_ + (size_t)(r0 + tx);
            g_xhi[idx] = hi;
            g_xlo[idx] = lo;
        }
    }
}

// ---------------------------------------------------------------------------
// Kernel 2: mma.sync bf16x3 GEMM per (o-tile, f).
// D[o(128), b(32)] = sum_i W[f,o,i] * xn[f,b,i]
// ---------------------------------------------------------------------------
__global__ void __launch_bounds__(256, 1)
gemm_kernel(const float* __restrict__ W,
            const float* __restrict__ bias)
{
    extern __shared__ char smem[];
    const uint32_t sb = smem_u32(smem);
    const int tid  = threadIdx.x;
    const int wid  = tid >> 5;
    const int lane = tid & 31;
    const int r    = lane >> 2;        // 0..7
    const int kq   = (lane & 3) << 1;  // 0,2,4,6

    const int f  = blockIdx.y;
    const int ot = blockIdx.x * OT;

    const float* __restrict__ Wf = W + (size_t)f * (O_ * I_);
    const __nv_bfloat16* __restrict__ xh = g_xhi + (size_t)f * R_;
    const __nv_bfloat16* __restrict__ xl = g_xlo + (size_t)f * R_;

    // W fp32 chunk loader: 128 rows x 64 floats into staged, padded smem
    auto issue_w = [&](int c, int stg) {
        const uint32_t dbase = sb + SM_WST + (uint32_t)stg * WST_BYTES;
        const int kbase = c * KC;
#pragma unroll
        for (int p = tid; p < OT * 16; p += 256) {       // 2048 float4s
            const int row = p >> 4, k4 = p & 15;
            int o = ot + row; if (o > O_ - 1) o = O_ - 1;
            cp16(dbase + (uint32_t)(row * (WST_STRIDE_F * 4) + k4 * 16),
                 Wf + (size_t)o * I_ + kbase + k4 * 4);
        }
    };

    // Prologue group 0: x tiles (hi+lo) + W chunk 0
#pragma unroll
    for (int p = tid; p < B_ * 64; p += 256) {           // 2048 per tensor
        const int b = p >> 6, kk = p & 63;               // kk = 16B unit
        cp16(sb + SM_XHI + (uint32_t)(b * XS_STRIDE_B + kk * 16), xh + b * 512 + kk * 8);
        cp16(sb + SM_XLO + (uint32_t)(b * XS_STRIDE_B + kk * 16), xl + b * 512 + kk * 8);
    }
    issue_w(0, 0); cp_commit();
    issue_w(1, 1); cp_commit();
    issue_w(2, 2); cp_commit();

    float acc[4][4];
#pragma unroll
    for (int n = 0; n < 4; n++)
#pragma unroll
        for (int j = 0; j < 4; j++) acc[n][j] = 0.f;

    const int wrow = (wid << 4) + r;                     // warp's A row (+8)

#pragma unroll 1
    for (int c = 0; c < NC; c++) {
        cp_wait<2>();            // group c (W chunk c, and x on c=0) resident
        __syncthreads();

        // convert fp32 -> bf16 hi/lo into padded tiles
        {
            const float4* st4 = reinterpret_cast<const float4*>(
                smem + SM_WST + (c % NST) * WST_BYTES +
                ((tid >> 1) * WST_STRIDE_F + (tid & 1) * 32) * 4);
            uint32_t hw[16], lw[16];
#pragma unroll
            for (int j = 0; j < 8; j++) {
                const float4 v = st4[j];
                const __nv_bfloat16 h0 = __float2bfloat16(v.x);
                const __nv_bfloat16 h1 = __float2bfloat16(v.y);
                const __nv_bfloat16 h2 = __float2bfloat16(v.z);
                const __nv_bfloat16 h3 = __float2bfloat16(v.w);
                const __nv_bfloat16 l0 = __float2bfloat16(v.x - __bfloat162float(h0));
                const __nv_bfloat16 l1 = __float2bfloat16(v.y - __bfloat162float(h1));
                const __nv_bfloat16 l2 = __float2bfloat16(v.z - __bfloat162float(h2));
                const __nv_bfloat16 l3 = __float2bfloat16(v.w - __bfloat162float(h3));
                hw[2*j]   = pack_bf2(h0, h1);
                hw[2*j+1] = pack_bf2(h2, h3);
                lw[2*j]   = pack_bf2(l0, l1);
                lw[2*j+1] = pack_bf2(l2, l3);
            }
            uint4* dh = reinterpret_cast<uint4*>(
                smem + SM_WHI + (tid >> 1) * WBF_STRIDE_B + (tid & 1) * 64);
            uint4* dl = reinterpret_cast<uint4*>(
                smem + SM_WLO + (tid >> 1) * WBF_STRIDE_B + (tid & 1) * 64);
#pragma unroll
            for (int j = 0; j < 4; j++) {
                dh[j] = reinterpret_cast<const uint4*>(hw)[j];
                dl[j] = reinterpret_cast<const uint4*>(lw)[j];
            }
        }
        __syncthreads();

        // MMA phase: 4 k-steps x (hi*hi + hi*lo + lo*hi)
        {
            const char* ahb = smem + SM_WHI + wrow * WBF_STRIDE_B + kq * 2;
            const char* alb = smem + SM_WLO + wrow * WBF_STRIDE_B + kq * 2;
            const char* bhb = smem + SM_XHI + r * XS_STRIDE_B + (c * KC + kq) * 2;
            const char* blb = smem + SM_XLO + r * XS_STRIDE_B + (c * KC + kq) * 2;
#pragma unroll
            for (int ks = 0; ks < 4; ks++) {
                const int ko = ks * 32;                  // 16 bf16 per k-step
                uint32_t ah[4], al[4];
                ah[0] = lds32(ahb + ko);
                ah[1] = lds32(ahb + ko + 8 * WBF_STRIDE_B);
                ah[2] = lds32(ahb + ko + 16);
                ah[3] = lds32(ahb + ko + 8 * WBF_STRIDE_B + 16);
                al[0] = lds32(alb + ko);
                al[1] = lds32(alb + ko + 8 * WBF_STRIDE_B);
                al[2] = lds32(alb + ko + 16);
                al[3] = lds32(alb + ko + 8 * WBF_STRIDE_B + 16);
#pragma unroll
                for (int nt = 0; nt < 4; nt++) {
                    const int no = nt * 8 * XS_STRIDE_B;
                    const uint32_t bh0 = lds32(bhb + no + ko);
                    const uint32_t bh1 = lds32(bhb + no + ko + 16);
                    const uint32_t bl0 = lds32(blb + no + ko);
                    const uint32_t bl1 = lds32(blb + no + ko + 16);
                    mma16816(acc[nt], ah, bh0, bh1);
                    mma16816(acc[nt], ah, bl0, bl1);
                    mma16816(acc[nt], al, bh0, bh1);
                }
            }
        }

        // prefetch W chunk c+3 into the stage convert just drained
        if (c + 3 < NC) issue_w(c + 3, c % NST);
        cp_commit();                                     // unconditional: keeps group count aligned
    }

    // Epilogue: g_out[f][o][b] += bias  (coalesced STG.64 pairs)
    {
        const int o0 = ot + wrow;
        const int ob0 = (o0     < O_) ? o0     : O_ - 1;
        const int ob1 = (o0 + 8 < O_) ? o0 + 8 : O_ - 1;
        const float bv0 = bias[(size_t)f * O_ + ob0];
        const float bv1 = bias[(size_t)f * O_ + ob1];
        float* base0 = g_out + ((size_t)f * OPAD + o0)     * B_ + kq;
        float* base1 = g_out + ((size_t)f * OPAD + o0 + 8) * B_ + kq;
#pragma unroll
        for (int nt = 0; nt < 4; nt++) {
            float2 v01 = make_float2(acc[nt][0] + bv0, acc[nt][1] + bv0);
            float2 v23 = make_float2(acc[nt][2] + bv1, acc[nt][3] + bv1);
            *reinterpret_cast<float2*>(base0 + nt * 8) = v01;
            *reinterpret_cast<float2*>(base1 + nt * 8) = v23;
        }
    }
}

// ---------------------------------------------------------------------------
// Kernel 3: g_out[f][o][b] -> out[b][o][f]
// ---------------------------------------------------------------------------
__global__ void out_transpose_kernel(float* __restrict__ out)
{
    __shared__ float s[32][33];
    const int o  = blockIdx.x;
    const int f0 = blockIdx.y * 32;
    const int tx = threadIdx.x, ty = threadIdx.y;

    const int f = f0 + ty;
    if (f < F_)
        s[ty][tx] = g_out[((size_t)f * OPAD + o) * B_ + tx];
    __syncthreads();

    const int ff = f0 + tx;
    if (ff < F_)
        out[(size_t)ty * (O_ * F_) + (size_t)o * F_ + ff] = s[tx][ty];
}

// ---------------------------------------------------------------------------
// Launch
// ---------------------------------------------------------------------------
extern "C" void kernel_launch(void* const* d_in, const int* in_sizes, int n_in,
                              void* d_out, int out_size)
{
    const float* x     = (const float*)d_in[0];
    const float* W     = (const float*)d_in[1];
    const float* bias  = (const float*)d_in[2];
    const float* gamma = (const float*)d_in[3];
    const float* beta  = (const float*)d_in[4];
    const float* rmean = (const float*)d_in[5];
    const float* rvar  = (const float*)d_in[6];
    float* out = (float*)d_out;
    (void)in_sizes; (void)n_in; (void)out_size;

    cudaFuncSetAttribute(gemm_kernel,
                         cudaFuncAttributeMaxDynamicSharedMemorySize, SMEM_BYTES);

    norm_transpose_kernel<<<dim3(11, R_ / 32), dim3(32, 8)>>>(x, gamma, beta,
                                                              rmean, rvar);
    gemm_kernel<<<dim3(OPAD / OT, F_), 256, SMEM_BYTES>>>(W, bias);
    out_transpose_kernel<<<dim3(O_, 11), dim3(32, 32)>>>(out);
}

// round 10
// speedup vs baseline: 1.0691x; 1.0547x over previous
#include <cuda_runtime.h>
#include <cstdint>

// Problem constants
#define B_   32
#define I_   512
#define F_   321
#define O_   720
#define OPAD 768
#define R_   (B_ * I_)
#define EPSV 1e-5f

// GEMM tiling
#define OT   128              // o rows per CTA
#define KC   32               // k per W chunk
#define NCH  (I_ / KC)        // 16 chunks

// smem strides/sizes
#define AST     36                    // W tile row stride (words): 32 + 4 pad
#define ABYTES  (OT * AST * 4)        // 18432 per buffer
#define XSTW    516                   // x row stride (words): 512 + 4 pad
#define XBYTES  (B_ * XSTW * 4)       // 66048
#define SM_X    0
#define SM_A    XBYTES
#define SMEM_BYTES (SM_A + 2 * ABYTES)   // 102912 -> 2 CTAs/SM

// device scratch
__device__ __align__(16) float g_xt[(size_t)F_ * R_];
__device__ __align__(16) float g_out[(size_t)F_ * OPAD * B_];

// ---- helpers ----
__device__ __forceinline__ uint32_t smem_u32(const void* p) {
    uint32_t a;
    asm("{ .reg .u64 t; cvta.to.shared.u64 t, %1; cvt.u32.u64 %0, t; }"
        : "=r"(a) : "l"(p));
    return a;
}
__device__ __forceinline__ void cp16(uint32_t dst, const void* src) {
    asm volatile("cp.async.cg.shared.global [%0], [%1], 16;\n" :: "r"(dst), "l"(src));
}
__device__ __forceinline__ void cp_commit() {
    asm volatile("cp.async.commit_group;\n");
}
template <int N>
__device__ __forceinline__ void cp_wait() {
    asm volatile("cp.async.wait_group %0;\n" :: "n"(N));
}
// packed f32x2 FMA: d(lo,hi) += a(lo,hi) * b(lo,hi)  [Blackwell FFMA2]
__device__ __forceinline__ void ffma2(unsigned long long& d,
                                      unsigned long long a,
                                      unsigned long long b) {
    asm("fma.rn.f32x2 %0, %1, %2, %0;" : "+l"(d) : "l"(a), "l"(b));
}
__device__ __forceinline__ float hsum2(unsigned long long v) {
    return __uint_as_float((unsigned)v) + __uint_as_float((unsigned)(v >> 32));
}

// ---------------------------------------------------------------------------
// Kernel 1: normalize + transpose  x[b,i,f] -> g_xt[f, b*512+i]
// ---------------------------------------------------------------------------
__global__ void norm_transpose_kernel(const float* __restrict__ x,
                                      const float* __restrict__ gamma,
                                      const float* __restrict__ beta,
                                      const float* __restrict__ rmean,
                                      const float* __restrict__ rvar)
{
    __shared__ float s[32][33];
    const int f0 = blockIdx.x * 32;
    const int r0 = blockIdx.y * 32;
    const int tx = threadIdx.x, ty = threadIdx.y;

    const int f = f0 + tx;
    float inv = 0.f, shift = 0.f;
    if (f < F_) {
        inv   = gamma[f] * rsqrtf(rvar[f] + EPSV);
        shift = beta[f] - rmean[f] * inv;
    }
#pragma unroll
    for (int k = 0; k < 4; k++) {
        const int rl = ty + k * 8;
        float v = (f < F_) ? x[(size_t)(r0 + rl) * F_ + f] : 0.f;
        s[rl][tx] = v * inv + shift;
    }
    __syncthreads();
#pragma unroll
    for (int k = 0; k < 4; k++) {
        const int fl = ty + k * 8;
        const int ff = f0 + fl;
        if (ff < F_)
            g_xt[(size_t)ff * R_ + (size_t)(r0 + tx)] = s[tx][fl];
    }
}

// ---------------------------------------------------------------------------
// Kernel 2: fp32 GEMM via packed FFMA2 (fma.rn.f32x2), k-packed operands.
// D[o(128), b(32)] = sum_i W[f,o,i] * xn[f,b,i]; writes g_out[f][o][b]+bias.
// Thread (og, bg): 8 o's (o = ot + og + 16*j) x 2 b's (b = 2*bg, 2*bg+1).
// ---------------------------------------------------------------------------
__global__ void __launch_bounds__(256, 2)
gemm_kernel(const float* __restrict__ W,
            const float* __restrict__ bias)
{
    extern __shared__ char smem[];
    const uint32_t sb = smem_u32(smem);
    const int tid = threadIdx.x;
    const int bg  = tid & 15;          // b-pair index
    const int og  = tid >> 4;          // o base (interleaved, stride 16)

    const int f  = blockIdx.y;
    const int ot = blockIdx.x * OT;

    const float* __restrict__ Wf = W + (size_t)f * (O_ * I_);
    const float* __restrict__ xt = g_xt + (size_t)f * R_;

    // W fp32 chunk loader: 128 rows x 32 floats (row = smem row = o - ot)
    auto issue_w = [&](int c, int buf) {
        const uint32_t dbase = sb + SM_A + (uint32_t)buf * ABYTES;
        const int kbase = c * KC;
#pragma unroll
        for (int p = tid; p < OT * 8; p += 256) {        // 1024 float4
            const int row = p >> 3, k4 = p & 7;
            int o = ot + row; if (o > O_ - 1) o = O_ - 1;
            cp16(dbase + (uint32_t)(row * (AST * 4) + k4 * 16),
                 Wf + (size_t)o * I_ + kbase + k4 * 4);
        }
    };

    // Group 0: full x tile + W chunk 0; Group 1: W chunk 1
#pragma unroll
    for (int p = tid; p < B_ * 128; p += 256) {          // 4096 float4
        const int b = p >> 7, k4 = p & 127;
        cp16(sb + SM_X + (uint32_t)(b * (XSTW * 4) + k4 * 16),
             xt + b * 512 + k4 * 4);
    }
    issue_w(0, 0); cp_commit();
    issue_w(1, 1); cp_commit();

    unsigned long long acc[8][2];
#pragma unroll
    for (int j = 0; j < 8; j++) { acc[j][0] = 0ULL; acc[j][1] = 0ULL; }

    const char* bb0 = smem + SM_X + (size_t)(bg * 2    ) * (XSTW * 4);
    const char* bb1 = smem + SM_X + (size_t)(bg * 2 + 1) * (XSTW * 4);

#pragma unroll 1
    for (int c = 0; c < NCH; c++) {
        cp_wait<1>();
        __syncthreads();

        const char* ab = smem + SM_A + (c & 1) * ABYTES + og * (AST * 4);
        const int xko = c * (KC * 4);
#pragma unroll
        for (int s = 0; s < 8; s++) {                    // 4 k's per step
            const int kb = s * 16;
            ulonglong2 a[8];
#pragma unroll
            for (int j = 0; j < 8; j++)
                a[j] = *reinterpret_cast<const ulonglong2*>(
                    ab + j * (16 * AST * 4) + kb);
            const ulonglong2 b0 =
                *reinterpret_cast<const ulonglong2*>(bb0 + xko + kb);
            const ulonglong2 b1 =
                *reinterpret_cast<const ulonglong2*>(bb1 + xko + kb);
#pragma unroll
            for (int j = 0; j < 8; j++) {
                ffma2(acc[j][0], a[j].x, b0.x);
                ffma2(acc[j][0], a[j].y, b0.y);
                ffma2(acc[j][1], a[j].x, b1.x);
                ffma2(acc[j][1], a[j].y, b1.y);
            }
        }

        __syncthreads();                 // buffer (c&1) free to refill
        if (c + 2 < NCH) issue_w(c + 2, c & 1);
        cp_commit();                     // unconditional: group count stays aligned
    }

    // Epilogue: horizontal add of k-packed halves, +bias, store g_out[f][o][b]
#pragma unroll
    for (int j = 0; j < 8; j++) {
        const int o  = ot + og + j * 16;
        const int oc = (o < O_) ? o : O_ - 1;
        const float bv = bias[(size_t)f * O_ + oc];
        float2 v;
        v.x = hsum2(acc[j][0]) + bv;
        v.y = hsum2(acc[j][1]) + bv;
        *reinterpret_cast<float2*>(
            g_out + ((size_t)f * OPAD + o) * B_ + bg * 2) = v;
    }
}

// ---------------------------------------------------------------------------
// Kernel 3: g_out[f][o][b] -> out[b][o][f]
// ---------------------------------------------------------------------------
__global__ void out_transpose_kernel(float* __restrict__ out)
{
    __shared__ float s[32][33];
    const int o  = blockIdx.x;
    const int f0 = blockIdx.y * 32;
    const int tx = threadIdx.x, ty = threadIdx.y;

    const int f = f0 + ty;
    if (f < F_)
        s[ty][tx] = g_out[((size_t)f * OPAD + o) * B_ + tx];
    __syncthreads();

    const int ff = f0 + tx;
    if (ff < F_)
        out[(size_t)ty * (O_ * F_) + (size_t)o * F_ + ff] = s[tx][ty];
}

// ---------------------------------------------------------------------------
// Launch
// ---------------------------------------------------------------------------
extern "C" void kernel_launch(void* const* d_in, const int* in_sizes, int n_in,
                              void* d_out, int out_size)
{
    const float* x     = (const float*)d_in[0];
    const float* W     = (const float*)d_in[1];
    const float* bias  = (const float*)d_in[2];
    const float* gamma = (const float*)d_in[3];
    const float* beta  = (const float*)d_in[4];
    const float* rmean = (const float*)d_in[5];
    const float* rvar  = (const float*)d_in[6];
    float* out = (float*)d_out;
    (void)in_sizes; (void)n_in; (void)out_size;

    cudaFuncSetAttribute(gemm_kernel,
                         cudaFuncAttributeMaxDynamicSharedMemorySize, SMEM_BYTES);

    norm_transpose_kernel<<<dim3(11, R_ / 32), dim3(32, 8)>>>(x, gamma, beta,
                                                              rmean, rvar);
    gemm_kernel<<<dim3(OPAD / OT, F_), 256, SMEM_BYTES>>>(W, bias);
    out_transpose_kernel<<<dim3(O_, 11), dim3(32, 32)>>>(out);
}

// round 14
// speedup vs baseline: 2.3466x; 2.1948x over previous
#include <cuda_runtime.h>
#include <cuda_fp16.h>
#include <cstdint>

// Problem constants
#define B_   32
#define I_   512
#define F_   321
#define O_   720
#define OPAD 768
#define R_   (B_ * I_)
#define EPSV 1e-5f

// GEMM tiling
#define OT   128              // o rows per CTA
#define KC   64               // k per chunk
#define NCH  (I_ / KC)        // 8 chunks

// smem layout: strides chosen so fragment banks = (4r+q) -> conflict-free
// (row stride in words ≡ 4 mod 32)
#define XROWB  1040                    // x fp16 row: 1024B data + 16B pad
#define XBYTES (B_ * XROWB)            // 33280
#define WROWB  144                     // W fp16 row: 128B data + 16B pad
#define WBYTES (OT * WROWB)            // 18432 per buffer
#define SM_XH  0
#define SM_WH  XBYTES
#define SMEM_BYTES (SM_XH + XBYTES + 2 * WBYTES)   // 70144 -> 2 CTAs/SM

// device scratch
__device__ __align__(16) __half g_xh[(size_t)F_ * R_];
__device__ __align__(16) float  g_out[(size_t)F_ * OPAD * B_];

// ---- helpers ----
__device__ __forceinline__ uint32_t smem_u32(const void* p) {
    uint32_t a;
    asm("{ .reg .u64 t; cvta.to.shared.u64 t, %1; cvt.u32.u64 %0, t; }"
        : "=r"(a) : "l"(p));
    return a;
}
__device__ __forceinline__ void cp16(uint32_t dst, const void* src) {
    asm volatile("cp.async.cg.shared.global [%0], [%1], 16;\n" :: "r"(dst), "l"(src));
}
__device__ __forceinline__ void cp_commit() {
    asm volatile("cp.async.commit_group;\n");
}
template <int N>
__device__ __forceinline__ void cp_wait() {
    asm volatile("cp.async.wait_group %0;\n" :: "n"(N));
}
__device__ __forceinline__ void mma16816(float* acc, const uint32_t a[4],
                                         uint32_t b0, uint32_t b1) {
    asm volatile(
        "mma.sync.aligned.m16n8k16.row.col.f32.f16.f16.f32 "
        "{%0,%1,%2,%3}, {%4,%5,%6,%7}, {%8,%9}, {%0,%1,%2,%3};\n"
        : "+f"(acc[0]), "+f"(acc[1]), "+f"(acc[2]), "+f"(acc[3])
        : "r"(a[0]), "r"(a[1]), "r"(a[2]), "r"(a[3]), "r"(b0), "r"(b1));
}
__device__ __forceinline__ uint32_t h2u(__half2 h) {
    return *reinterpret_cast<uint32_t*>(&h);
}

// ---------------------------------------------------------------------------
// Kernel 1: normalize + transpose + fp16 convert
// x[b,i,f] -> g_xh[f, b*512+i]
// ---------------------------------------------------------------------------
__global__ void norm_transpose_kernel(const float* __restrict__ x,
                                      const float* __restrict__ gamma,
                                      const float* __restrict__ beta,
                                      const float* __restrict__ rmean,
                                      const float* __restrict__ rvar)
{
    __shared__ float s[32][33];
    const int f0 = blockIdx.x * 32;
    const int r0 = blockIdx.y * 32;
    const int tx = threadIdx.x, ty = threadIdx.y;

    const int f = f0 + tx;
    float inv = 0.f, shift = 0.f;
    if (f < F_) {
        inv   = gamma[f] * rsqrtf(rvar[f] + EPSV);
        shift = beta[f] - rmean[f] * inv;
    }
#pragma unroll
    for (int k = 0; k < 4; k++) {
        const int rl = ty + k * 8;
        float v = (f < F_) ? x[(size_t)(r0 + rl) * F_ + f] : 0.f;
        s[rl][tx] = v * inv + shift;
    }
    __syncthreads();
#pragma unroll
    for (int k = 0; k < 4; k++) {
        const int fl = ty + k * 8;
        const int ff = f0 + fl;
        if (ff < F_)
            g_xh[(size_t)ff * R_ + (size_t)(r0 + tx)] = __float2half_rn(s[tx][fl]);
    }
}

// ---------------------------------------------------------------------------
// Kernel 2: fp16 single-product mma.sync GEMM per (o-tile, f).
// D[o(128), b(32)] = sum_i W[f,o,i] * xn[f,b,i]; writes g_out[f][o][b]+bias.
// W converted fp32->fp16 in registers (LDG -> cvt -> STS), double-buffered.
// ---------------------------------------------------------------------------
__global__ void __launch_bounds__(256, 2)
gemm_kernel(const float* __restrict__ W,
            const float* __restrict__ bias)
{
    extern __shared__ char smem[];
    const uint32_t sb = smem_u32(smem);
    const int tid  = threadIdx.x;
    const int wid  = tid >> 5;
    const int lane = tid & 31;
    const int r    = lane >> 2;        // 0..7
    const int q    = lane & 3;         // 0..3

    const int f  = blockIdx.y;
    const int ot = blockIdx.x * OT;

    const float* __restrict__ Wf = W + (size_t)f * (O_ * I_);
    const __half* __restrict__ xh = g_xh + (size_t)f * R_;

    // x tile (32 x 512 fp16) -> smem, cp.async, single group
#pragma unroll
    for (int p = tid; p < B_ * 64; p += 256) {           // 2048 x 16B
        const int b = p >> 6, u = p & 63;
        cp16(sb + SM_XH + (uint32_t)(b * XROWB + u * 16), xh + b * 512 + u * 8);
    }
    cp_commit();

    // W register staging: thread owns (rowbase = tid>>4, k4 = tid&15),
    // rows jj*16 + rowbase, 1 float4 each -> fully coalesced LDG.128.
    const int rb = tid >> 4, k4 = tid & 15;
    float4 wreg[8];
    auto ldg_chunk = [&](int c) {
        const float* src = Wf + (size_t)(c * KC) + k4 * 4;
#pragma unroll
        for (int jj = 0; jj < 8; jj++) {
            int o = ot + jj * 16 + rb;
            if (o > O_ - 1) o = O_ - 1;
            wreg[jj] = *reinterpret_cast<const float4*>(src + (size_t)o * I_);
        }
    };
    auto stw = [&](int buf) {
        char* dst = smem + SM_WH + buf * WBYTES;
#pragma unroll
        for (int jj = 0; jj < 8; jj++) {
            const int row = jj * 16 + rb;
            const __half2 h0 = __floats2half2_rn(wreg[jj].x, wreg[jj].y);
            const __half2 h1 = __floats2half2_rn(wreg[jj].z, wreg[jj].w);
            *reinterpret_cast<uint2*>(dst + row * WROWB + k4 * 8) =
                make_uint2(h2u(h0), h2u(h1));
        }
    };

    ldg_chunk(0);

    float acc[4][4];
#pragma unroll
    for (int n = 0; n < 4; n++)
#pragma unroll
        for (int j = 0; j < 4; j++) acc[n][j] = 0.f;

    const uint32_t* xt = reinterpret_cast<const uint32_t*>(smem + SM_XH);
    const int arow = wid * 16 + r;                       // warp A row (+8)

#pragma unroll 1
    for (int c = 0; c < NCH; c++) {
        stw(c & 1);
        if (c == 0) cp_wait<0>();
        __syncthreads();
        if (c + 1 < NCH) ldg_chunk(c + 1);

        const uint32_t* wt = reinterpret_cast<const uint32_t*>(
            smem + SM_WH + (c & 1) * WBYTES);
        const int xko = c * (KC / 2);                    // k word offset
#pragma unroll
        for (int ks = 0; ks < 4; ks++) {
            const int aw = arow * (WROWB / 4) + ks * 8 + q;
            uint32_t a[4];
            a[0] = wt[aw];
            a[1] = wt[aw + 8 * (WROWB / 4)];
            a[2] = wt[aw + 4];
            a[3] = wt[aw + 8 * (WROWB / 4) + 4];
#pragma unroll
            for (int nt = 0; nt < 4; nt++) {
                const int bw = (nt * 8 + r) * (XROWB / 4) + xko + ks * 8 + q;
                mma16816(acc[nt], a, xt[bw], xt[bw + 4]);
            }
        }
        // next stw targets buf((c+1)&1); its last readers (MMA of chunk c-1)
        // finished before this iteration's __syncthreads -> one sync/chunk.
    }

    // Epilogue: g_out[f][o][b] += bias
    {
        const int o0  = ot + arow;                       // row of c0/c1
        const int ob0 = (o0     < O_) ? o0     : O_ - 1;
        const int ob1 = (o0 + 8 < O_) ? o0 + 8 : O_ - 1;
        const float bv0 = bias[(size_t)f * O_ + ob0];
        const float bv1 = bias[(size_t)f * O_ + ob1];
        float* base0 = g_out + ((size_t)f * OPAD + o0)     * B_ + q * 2;
        float* base1 = g_out + ((size_t)f * OPAD + o0 + 8) * B_ + q * 2;
#pragma unroll
        for (int nt = 0; nt < 4; nt++) {
            *reinterpret_cast<float2*>(base0 + nt * 8) =
                make_float2(acc[nt][0] + bv0, acc[nt][1] + bv0);
            *reinterpret_cast<float2*>(base1 + nt * 8) =
                make_float2(acc[nt][2] + bv1, acc[nt][3] + bv1);
        }
    }
}

// ---------------------------------------------------------------------------
// Kernel 3: g_out[f][o][b] -> out[b][o][f]
// ---------------------------------------------------------------------------
__global__ void out_transpose_kernel(float* __restrict__ out)
{
    __shared__ float s[32][33];
    const int o  = blockIdx.x;
    const int f0 = blockIdx.y * 32;
    const int tx = threadIdx.x, ty = threadIdx.y;

    const int f = f0 + ty;
    if (f < F_)
        s[ty][tx] = g_out[((size_t)f * OPAD + o) * B_ + tx];
    __syncthreads();

    const int ff = f0 + tx;
    if (ff < F_)
        out[(size_t)ty * (O_ * F_) + (size_t)o * F_ + ff] = s[tx][ty];
}

// ---------------------------------------------------------------------------
// Launch
// ---------------------------------------------------------------------------
extern "C" void kernel_launch(void* const* d_in, const int* in_sizes, int n_in,
                              void* d_out, int out_size)
{
    const float* x     = (const float*)d_in[0];
    const float* W     = (const float*)d_in[1];
    const float* bias  = (const float*)d_in[2];
    const float* gamma = (const float*)d_in[3];
    const float* beta  = (const float*)d_in[4];
    const float* rmean = (const float*)d_in[5];
    const float* rvar  = (const float*)d_in[6];
    float* out = (float*)d_out;
    (void)in_sizes; (void)n_in; (void)out_size;

    cudaFuncSetAttribute(gemm_kernel,
                         cudaFuncAttributeMaxDynamicSharedMemorySize, SMEM_BYTES);

    norm_transpose_kernel<<<dim3(11, R_ / 32), dim3(32, 8)>>>(x, gamma, beta,
                                                              rmean, rvar);
    gemm_kernel<<<dim3(OPAD / OT, F_), 256, SMEM_BYTES>>>(W, bias);
    out_transpose_kernel<<<dim3(O_, 11), dim3(32, 32)>>>(out);
}